// round 9
// baseline (speedup 1.0000x reference)
#include <cuda_runtime.h>

#define N_DOF 16
#define BATCH 64
#define SEQ 8192
#define CHUNK 64
#define NCHUNK (SEQ/CHUNK)          // 128
#define GRP 16
#define NGROUP (NCHUNK/GRP)         // 8
#define NSTATE 48
#define BSD ((size_t)BATCH*(size_t)SEQ*(size_t)N_DOF)

#define DTc 0.01f
#define CU_ 2.5e-5f   // (0.5-beta)*dt*dt
#define CV_ 0.005f    // (1-gamma)*dt
#define BU_ 2.5e-5f   // beta*dt*dt
#define BV_ 0.005f    // gamma*dt

// ---------------- packed f32x2 helpers (Blackwell FFMA2) ----------------
typedef unsigned long long u64;

__device__ __forceinline__ u64 ffma2(u64 a, u64 b, u64 c) {
    u64 d;
    asm("fma.rn.f32x2 %0, %1, %2, %3;" : "=l"(d) : "l"(a), "l"(b), "l"(c));
    return d;
}
__device__ __forceinline__ u64 fadd2(u64 a, u64 b) {
    u64 d;
    asm("add.rn.f32x2 %0, %1, %2;" : "=l"(d) : "l"(a), "l"(b));
    return d;
}
__device__ __forceinline__ float2 unpack2(u64 d) {
    float2 f;
    asm("mov.b64 {%0, %1}, %2;" : "=f"(f.x), "=f"(f.y) : "l"(d));
    return f;
}

// ---------------- scratch (device globals; no runtime allocation) ----------------
__device__ __align__(16) float g_Af[256];      // K_eff^{-1}
__device__ __align__(16) float g_Wuv[16*32];   // interleaved pairs: (Au[i][j], Av[i][j])
__device__ __align__(16) float g_TL[NSTATE*NSTATE];    // T^CHUNK
__device__ __align__(16) float g_TLG[NSTATE*NSTATE];   // T^(CHUNK*GRP)
__device__ __align__(16) float g_e[(NCHUNK-1)*BATCH*NSTATE];
__device__ __align__(16) float g_init[NCHUNK*BATCH*NSTATE];
__device__ __align__(16) float g_pend[(NGROUP-1)*BATCH*NSTATE];
// PhiS[b][i][t'] = (A_f @ F[b, t'+1, :])[i]  for t' in [0, SEQ-1); PhiS[..][SEQ-1] = 0
__device__ __align__(16) float g_PhiS[(size_t)BATCH*N_DOF*SEQ];

// ---------------- K0: setup ----------------
__device__ void invert16(const float* A, float* Ainv, double (*aug)[34], int tid)
{
    if (tid < 16) {
        #pragma unroll
        for (int j = 0; j < 16; j++) {
            aug[tid][j]      = (double)A[tid*16 + j];
            aug[tid][16 + j] = (tid == j) ? 1.0 : 0.0;
        }
    }
    __syncthreads();
    for (int k = 0; k < 16; k++) {
        if (tid == k) {
            double p = 1.0 / aug[k][k];
            #pragma unroll
            for (int j = 0; j < 32; j++) aug[k][j] *= p;
        }
        __syncthreads();
        if (tid < 16 && tid != k) {
            double f = aug[tid][k];
            #pragma unroll
            for (int j = 0; j < 32; j++) aug[tid][j] -= f * aug[k][j];
        }
        __syncthreads();
    }
    if (tid < 16) {
        #pragma unroll
        for (int j = 0; j < 16; j++) Ainv[tid*16 + j] = (float)aug[tid][16 + j];
    }
    __syncthreads();
}

__global__ void __launch_bounds__(1024) setup_kernel(const float* __restrict__ F,
                             const float* __restrict__ M,
                             const float* __restrict__ C,
                             const float* __restrict__ K,
                             float* __restrict__ out)
{
    __shared__ double aug[16][34];
    __shared__ float sM[256], sC[256], sK[256], sKe[256];
    __shared__ float sMinv[256], sAf[256], sAv[256], sAu[256];
    __shared__ __align__(16) float sT[NSTATE*NSTATE];
    __shared__ __align__(16) float sT2[NSTATE*NSTATE];

    const int tid = threadIdx.x;

    if (tid < 256) { sM[tid] = M[tid]; sC[tid] = C[tid]; sK[tid] = K[tid]; }
    __syncthreads();

    invert16(sM, sMinv, aug, tid);

    if (tid < 256) sKe[tid] = sM[tid] + 0.5f*DTc*sC[tid] + 0.25f*DTc*DTc*sK[tid];
    __syncthreads();
    invert16(sKe, sAf, aug, tid);

    // A_v = A_f @ C, A_u = A_f @ K
    if (tid < 256) {
        int i = tid >> 4, j = tid & 15;
        float sv = 0.f, su = 0.f;
        #pragma unroll
        for (int k = 0; k < 16; k++) {
            sv = fmaf(sAf[i*16 + k], sC[k*16 + j], sv);
            su = fmaf(sAf[i*16 + k], sK[k*16 + j], su);
        }
        sAv[tid] = sv; sAu[tid] = su;
    }
    __syncthreads();

    if (tid < 256) {
        g_Af[tid] = sAf[tid];
        int i = tid >> 4, j = tid & 15;
        g_Wuv[i*32 + 2*j]     = sAu[tid];
        g_Wuv[i*32 + 2*j + 1] = sAv[tid];
    }

    // Build T (48x48) by pushing state basis vectors through one step (f = 0)
    if (tid < NSTATE) {
        float u[16], v[16], a[16];
        #pragma unroll
        for (int j = 0; j < 16; j++) {
            u[j] = (tid == j)      ? 1.f : 0.f;
            v[j] = (tid == j + 16) ? 1.f : 0.f;
            a[j] = (tid == j + 32) ? 1.f : 0.f;
        }
        float up[16], vp[16], an[16];
        #pragma unroll
        for (int i = 0; i < 16; i++) {
            up[i] = fmaf(CU_, a[i], fmaf(DTc, v[i], u[i]));
            vp[i] = fmaf(CV_, a[i], v[i]);
        }
        #pragma unroll
        for (int i = 0; i < 16; i++) {
            float s = 0.f;
            #pragma unroll
            for (int j = 0; j < 16; j++)
                s = fmaf(sAv[i*16 + j], vp[j], fmaf(sAu[i*16 + j], up[j], s));
            an[i] = -s;
        }
        #pragma unroll
        for (int i = 0; i < 16; i++) {
            sT[(i)     *NSTATE + tid] = fmaf(BU_, an[i], up[i]);
            sT[(16 + i)*NSTATE + tid] = fmaf(BV_, an[i], vp[i]);
            sT[(32 + i)*NSTATE + tid] = an[i];
        }
    }
    __syncthreads();

    // 10 squarings: after 6 -> T^64 (g_TL); after 10 -> T^1024 (g_TLG)
    float* Asq = sT;
    float* Bsq = sT2;
    for (int it = 0; it < 10; it++) {
        for (int e = tid; e < NSTATE*NSTATE; e += 1024) {
            int r = e / NSTATE, cc = e % NSTATE;
            const float4* rowp = reinterpret_cast<const float4*>(Asq + r*NSTATE);
            float s0 = 0.f, s1 = 0.f, s2 = 0.f, s3 = 0.f;
            #pragma unroll
            for (int q = 0; q < 12; q++) {
                float4 m = rowp[q];
                s0 = fmaf(m.x, Asq[(4*q    )*NSTATE + cc], s0);
                s1 = fmaf(m.y, Asq[(4*q + 1)*NSTATE + cc], s1);
                s2 = fmaf(m.z, Asq[(4*q + 2)*NSTATE + cc], s2);
                s3 = fmaf(m.w, Asq[(4*q + 3)*NSTATE + cc], s3);
            }
            Bsq[e] = (s0 + s1) + (s2 + s3);
        }
        __syncthreads();
        float* t = Asq; Asq = Bsq; Bsq = t;
        if (it == 5) {
            for (int e = tid; e < NSTATE*NSTATE; e += 1024) g_TL[e] = Asq[e];
        }
    }
    for (int e = tid; e < NSTATE*NSTATE; e += 1024) g_TLG[e] = Asq[e];

    // a0 = Minv @ F[b,0,:], write init_0 and t=0 output row
    if (tid < BATCH*16) {
        int b = tid >> 4, i = tid & 15;
        const float* f0p = F + (size_t)b * SEQ * N_DOF;
        float s = 0.f;
        #pragma unroll
        for (int j = 0; j < 16; j++) s = fmaf(sMinv[i*16 + j], f0p[j], s);
        float* ip = g_init + (size_t)b * NSTATE;
        ip[i] = 0.f; ip[16 + i] = 0.f; ip[32 + i] = s;
        size_t o = ((size_t)b * SEQ) * N_DOF + i;
        out[o] = 0.f; out[BSD + o] = 0.f; out[2*BSD + o] = s;
    }
}

// ---------------- K_phi: PhiS[b][i][t'] = (Af @ F[b][t'+1])[i], streaming ----------------
__global__ void __launch_bounds__(256) phi_kernel(const float* __restrict__ F)
{
    __shared__ float sAf[256];
    const int tid  = threadIdx.x;
    const int b    = blockIdx.y;
    const int tile = blockIdx.x;           // SEQ/256 tiles
    sAf[tid] = g_Af[tid];
    __syncthreads();

    const int tp = tile * 256 + tid;       // t'
    const int n  = tp + 1;                 // forcing time index

    float ph[16];
    if (n < SEQ) {
        const float4* fp = reinterpret_cast<const float4*>(F + ((size_t)b * SEQ + n) * N_DOF);
        const float4 f0 = fp[0], f1 = fp[1], f2 = fp[2], f3 = fp[3];
        #pragma unroll
        for (int i = 0; i < 16; i++) {
            const float4* ar = reinterpret_cast<const float4*>(sAf + i*16);
            const float4 a0 = ar[0], a1 = ar[1], a2 = ar[2], a3 = ar[3];
            float s0 = 0.f, s1 = 0.f;
            s0 = fmaf(a0.x, f0.x, s0); s1 = fmaf(a0.y, f0.y, s1);
            s0 = fmaf(a0.z, f0.z, s0); s1 = fmaf(a0.w, f0.w, s1);
            s0 = fmaf(a1.x, f1.x, s0); s1 = fmaf(a1.y, f1.y, s1);
            s0 = fmaf(a1.z, f1.z, s0); s1 = fmaf(a1.w, f1.w, s1);
            s0 = fmaf(a2.x, f2.x, s0); s1 = fmaf(a2.y, f2.y, s1);
            s0 = fmaf(a2.z, f2.z, s0); s1 = fmaf(a2.w, f2.w, s1);
            s0 = fmaf(a3.x, f3.x, s0); s1 = fmaf(a3.y, f3.y, s1);
            s0 = fmaf(a3.z, f3.z, s0); s1 = fmaf(a3.w, f3.w, s1);
            ph[i] = s0 + s1;
        }
    } else {
        #pragma unroll
        for (int i = 0; i < 16; i++) ph[i] = 0.f;
    }

    #pragma unroll
    for (int i = 0; i < 16; i++)
        g_PhiS[((size_t)b * N_DOF + i) * SEQ + tp] = ph[i];
}

// ---------------- K1 / K3: chunked scans ----------------
template<bool FINAL>
__global__ void __launch_bounds__(256, 3) scan_kernel(float* __restrict__ out)
{
    const int tid  = threadIdx.x;
    const int lane = tid & 15;
    const int su   = tid >> 4;                 // 0..15
    const int unit = blockIdx.x * 16 + su;
    const int b    = unit & (BATCH - 1);
    const int c    = unit >> 6;

    // exchange weights in registers, packed pairs (Au[j],Av[j])
    const ulonglong2* Wp = reinterpret_cast<const ulonglong2*>(g_Wuv + lane*32);
    const ulonglong2 w0 = Wp[0], w1 = Wp[1], w2 = Wp[2], w3 = Wp[3];
    const ulonglong2 w4 = Wp[4], w5 = Wp[5], w6 = Wp[6], w7 = Wp[7];

    float u, v, a;
    if (FINAL) {
        const float* ip = g_init + ((size_t)c * BATCH + b) * NSTATE;
        u = ip[lane]; v = ip[lane + 16]; a = ip[lane + 32];
    } else {
        u = 0.f; v = 0.f; a = 0.f;
    }

    __shared__ __align__(16) float2 sh[2][16][16];   // double-buffered exchange
    const int t0 = c * CHUNK;

    const float* php = g_PhiS + ((size_t)b * N_DOF + lane) * SEQ + t0;
    float4 ph = *reinterpret_cast<const float4*>(php);   // steps 0..3

    float* outu = out +          ((size_t)b * SEQ + t0 + 1) * N_DOF + lane;
    float* outv = outu + BSD;
    float* outa = outv + BSD;

    #pragma unroll 1
    for (int kg = 0; kg < CHUNK; kg += 4) {
        float4 phn = make_float4(0.f, 0.f, 0.f, 0.f);
        if (kg + 4 < CHUNK) phn = *reinterpret_cast<const float4*>(php + kg + 4);

        #pragma unroll
        for (int s = 0; s < 4; s++) {
            const float phv = (s == 0) ? ph.x : (s == 1) ? ph.y : (s == 2) ? ph.z : ph.w;
            const int buf = s & 1;

            const float up = fmaf(CU_, a, fmaf(DTc, v, u));
            const float vp = fmaf(CV_, a, v);
            sh[buf][su][lane] = make_float2(up, vp);
            __syncwarp();

            const ulonglong2* X2 = reinterpret_cast<const ulonglong2*>(sh[buf][su]);
            u64 accW0 = 0, accW1 = 0;
            {
                ulonglong2 x;
                x = X2[0]; accW0 = ffma2(w0.x, x.x, accW0); accW1 = ffma2(w0.y, x.y, accW1);
                x = X2[1]; accW0 = ffma2(w1.x, x.x, accW0); accW1 = ffma2(w1.y, x.y, accW1);
                x = X2[2]; accW0 = ffma2(w2.x, x.x, accW0); accW1 = ffma2(w2.y, x.y, accW1);
                x = X2[3]; accW0 = ffma2(w3.x, x.x, accW0); accW1 = ffma2(w3.y, x.y, accW1);
                x = X2[4]; accW0 = ffma2(w4.x, x.x, accW0); accW1 = ffma2(w4.y, x.y, accW1);
                x = X2[5]; accW0 = ffma2(w5.x, x.x, accW0); accW1 = ffma2(w5.y, x.y, accW1);
                x = X2[6]; accW0 = ffma2(w6.x, x.x, accW0); accW1 = ffma2(w6.y, x.y, accW1);
                x = X2[7]; accW0 = ffma2(w7.x, x.x, accW0); accW1 = ffma2(w7.y, x.y, accW1);
            }
            const float2 wS = unpack2(fadd2(accW0, accW1));
            const float an = phv - wS.x - wS.y;
            const float un = fmaf(BU_, an, up);
            const float vn = fmaf(BV_, an, vp);

            if (FINAL) {
                const int t = t0 + kg + s + 1;
                if (t < SEQ) {
                    const size_t off = (size_t)(kg + s) * N_DOF;
                    outu[off] = un;
                    outv[off] = vn;
                    outa[off] = an;
                }
            }
            u = un; v = vn; a = an;
        }
        ph = phn;
    }

    if (!FINAL) {
        float* ep = g_e + ((size_t)c * BATCH + b) * NSTATE;
        ep[lane] = u; ep[lane + 16] = v; ep[lane + 32] = a;
    }
}

// ---------------- chain helpers ----------------
__device__ __forceinline__ float matvec48(const ulonglong2* tl, const float* curv)
{
    const ulonglong2* c2 = reinterpret_cast<const ulonglong2*>(curv);
    u64 a0 = 0, a1 = 0, a2 = 0, a3 = 0;
    #pragma unroll
    for (int q = 0; q < 12; q += 4) {
        ulonglong2 x;
        x = c2[q];     a0 = ffma2(tl[q].x,     x.x, a0); a1 = ffma2(tl[q].y,     x.y, a1);
        x = c2[q + 1]; a2 = ffma2(tl[q + 1].x, x.x, a2); a3 = ffma2(tl[q + 1].y, x.y, a3);
        x = c2[q + 2]; a0 = ffma2(tl[q + 2].x, x.x, a0); a1 = ffma2(tl[q + 2].y, x.y, a1);
        x = c2[q + 3]; a2 = ffma2(tl[q + 3].x, x.x, a2); a3 = ffma2(tl[q + 3].y, x.y, a3);
    }
    const float2 s01 = unpack2(fadd2(a0, a1));
    const float2 s23 = unpack2(fadd2(a2, a3));
    return (s01.x + s01.y) + (s23.x + s23.y);
}

// ---- K2a: zero-init group partials (groups 0..NGROUP-2) ----
__global__ void __launch_bounds__(64) chain_zero_kernel()
{
    const int g = blockIdx.x;           // 0..NGROUP-2
    const int b = blockIdx.y;
    const int tid = threadIdx.x;        // 0..63
    const int i = tid;

    __shared__ __align__(16) float se[GRP*NSTATE];
    __shared__ __align__(16) float cur[2][NSTATE];

    for (int idx = tid; idx < GRP*NSTATE; idx += 64) {
        const int c = idx / NSTATE;
        const int j = idx - c * NSTATE;
        se[idx] = g_e[((size_t)(g*GRP + c) * BATCH + b) * NSTATE + j];
    }

    ulonglong2 tl[12];
    if (i < NSTATE) {
        const ulonglong2* tp = reinterpret_cast<const ulonglong2*>(g_TL + i*NSTATE);
        #pragma unroll
        for (int q = 0; q < 12; q++) tl[q] = tp[q];
        cur[0][i] = 0.f;
    }
    __syncthreads();

    int p = 0;
    float r = 0.f;
    for (int k = 0; k < GRP; k++) {
        if (i < NSTATE) {
            r = matvec48(tl, cur[p]) + se[k*NSTATE + i];
            cur[1 - p][i] = r;
        }
        __syncthreads();
        p ^= 1;
    }
    if (i < NSTATE)
        g_pend[((size_t)g * BATCH + b) * NSTATE + i] = r;
}

// ---- K2b: top chain across groups (per batch, 7 links with TLG) ----
__global__ void __launch_bounds__(NSTATE) chain_top_kernel()
{
    const int b = blockIdx.x;
    const int i = threadIdx.x;          // 0..47
    __shared__ __align__(16) float cur[2][NSTATE];

    ulonglong2 tlg[12];
    {
        const ulonglong2* tp = reinterpret_cast<const ulonglong2*>(g_TLG + i*NSTATE);
        #pragma unroll
        for (int q = 0; q < 12; q++) tlg[q] = tp[q];
    }
    cur[0][i] = g_init[(size_t)b * NSTATE + i];
    __syncthreads();

    int p = 0;
    for (int g = 0; g < NGROUP - 1; g++) {
        const float r = matvec48(tlg, cur[p]) + g_pend[((size_t)g * BATCH + b) * NSTATE + i];
        g_init[((size_t)((g + 1) * GRP) * BATCH + b) * NSTATE + i] = r;
        cur[1 - p][i] = r;
        __syncthreads();
        p ^= 1;
    }
}

// ---- K2c: per-group final chains (15 links from correct heads) ----
__global__ void __launch_bounds__(64) chain_final_kernel()
{
    const int g = blockIdx.x;           // 0..NGROUP-1
    const int b = blockIdx.y;
    const int tid = threadIdx.x;
    const int i = tid;

    __shared__ __align__(16) float se[(GRP-1)*NSTATE];
    __shared__ __align__(16) float cur[2][NSTATE];

    for (int idx = tid; idx < (GRP-1)*NSTATE; idx += 64) {
        const int c = idx / NSTATE;
        const int j = idx - c * NSTATE;
        se[idx] = g_e[((size_t)(g*GRP + c) * BATCH + b) * NSTATE + j];
    }

    ulonglong2 tl[12];
    if (i < NSTATE) {
        const ulonglong2* tp = reinterpret_cast<const ulonglong2*>(g_TL + i*NSTATE);
        #pragma unroll
        for (int q = 0; q < 12; q++) tl[q] = tp[q];
        cur[0][i] = g_init[((size_t)(g*GRP) * BATCH + b) * NSTATE + i];
    }
    __syncthreads();

    int p = 0;
    for (int k = 1; k < GRP; k++) {
        if (i < NSTATE) {
            const float r = matvec48(tl, cur[p]) + se[(k-1)*NSTATE + i];
            g_init[((size_t)(g*GRP + k) * BATCH + b) * NSTATE + i] = r;
            cur[1 - p][i] = r;
        }
        __syncthreads();
        p ^= 1;
    }
}

// ---------------- launch ----------------
extern "C" void kernel_launch(void* const* d_in, const int* in_sizes, int n_in,
                              void* d_out, int out_size)
{
    const float* F = (const float*)d_in[0];
    const float* M = (const float*)d_in[1];
    const float* C = (const float*)d_in[2];
    const float* K = (const float*)d_in[3];
    float* out = (float*)d_out;

    setup_kernel<<<1, 1024>>>(F, M, C, K, out);

    // forcing precompute: PhiS = Af @ F rows, transposed + shifted
    phi_kernel<<<dim3(SEQ/256, BATCH), 256>>>(F);

    // K1: zero-init local scans for chunks 0..NCHUNK-2
    scan_kernel<false><<<(NCHUNK - 1) * BATCH / 16, 256>>>(nullptr);

    // K2: two-level combine
    chain_zero_kernel<<<dim3(NGROUP - 1, BATCH), 64>>>();
    chain_top_kernel<<<BATCH, NSTATE>>>();
    chain_final_kernel<<<dim3(NGROUP, BATCH), 64>>>();

    // K3: final scans from correct initial states, all chunks
    scan_kernel<true><<<NCHUNK * BATCH / 16, 256>>>(out);
}

// round 10
// speedup vs baseline: 1.0867x; 1.0867x over previous
#include <cuda_runtime.h>

#define N_DOF 16
#define BATCH 64
#define SEQ 8192
#define CHUNK 128
#define NCHUNK (SEQ/CHUNK)          // 64
#define NSTATE 48
#define BSD ((size_t)BATCH*(size_t)SEQ*(size_t)N_DOF)

#define DTc 0.01f
#define CU_ 2.5e-5f   // (0.5-beta)*dt*dt
#define CV_ 0.005f    // (1-gamma)*dt
#define BU_ 2.5e-5f   // beta*dt*dt
#define BV_ 0.005f    // gamma*dt

// ---------------- packed f32x2 helpers (Blackwell FFMA2) ----------------
typedef unsigned long long u64;

__device__ __forceinline__ u64 ffma2(u64 a, u64 b, u64 c) {
    u64 d;
    asm("fma.rn.f32x2 %0, %1, %2, %3;" : "=l"(d) : "l"(a), "l"(b), "l"(c));
    return d;
}
__device__ __forceinline__ u64 fadd2(u64 a, u64 b) {
    u64 d;
    asm("add.rn.f32x2 %0, %1, %2;" : "=l"(d) : "l"(a), "l"(b));
    return d;
}
__device__ __forceinline__ float2 unpack2(u64 d) {
    float2 f;
    asm("mov.b64 {%0, %1}, %2;" : "=f"(f.x), "=f"(f.y) : "l"(d));
    return f;
}

// ---------------- scratch (device globals; no runtime allocation) ----------------
__device__ __align__(16) float g_Af[256];      // K_eff^{-1}
__device__ __align__(16) float g_Wuv[16*32];   // interleaved pairs: (Au[i][j], Av[i][j])
__device__ __align__(16) float g_TL[NSTATE*NSTATE];    // T^CHUNK
__device__ __align__(16) float g_e[(NCHUNK-1)*BATCH*NSTATE];
__device__ __align__(16) float g_init[NCHUNK*BATCH*NSTATE];
// PhiS[b][i][t'] = (A_f @ F[b, t'+1, :])[i]  for t' in [0, SEQ-1); PhiS[..][SEQ-1] = 0
__device__ __align__(16) float g_PhiS[(size_t)BATCH*N_DOF*SEQ];

// ---------------- K0: setup ----------------
__device__ void invert16(const float* A, float* Ainv, double (*aug)[34], int tid)
{
    if (tid < 16) {
        #pragma unroll
        for (int j = 0; j < 16; j++) {
            aug[tid][j]      = (double)A[tid*16 + j];
            aug[tid][16 + j] = (tid == j) ? 1.0 : 0.0;
        }
    }
    __syncthreads();
    for (int k = 0; k < 16; k++) {
        if (tid == k) {
            double p = 1.0 / aug[k][k];
            #pragma unroll
            for (int j = 0; j < 32; j++) aug[k][j] *= p;
        }
        __syncthreads();
        if (tid < 16 && tid != k) {
            double f = aug[tid][k];
            #pragma unroll
            for (int j = 0; j < 32; j++) aug[tid][j] -= f * aug[k][j];
        }
        __syncthreads();
    }
    if (tid < 16) {
        #pragma unroll
        for (int j = 0; j < 16; j++) Ainv[tid*16 + j] = (float)aug[tid][16 + j];
    }
    __syncthreads();
}

__global__ void __launch_bounds__(1024) setup_kernel(const float* __restrict__ F,
                             const float* __restrict__ M,
                             const float* __restrict__ C,
                             const float* __restrict__ K,
                             float* __restrict__ out)
{
    __shared__ double aug[16][34];
    __shared__ float sM[256], sC[256], sK[256], sKe[256];
    __shared__ float sMinv[256], sAf[256], sAv[256], sAu[256];
    __shared__ __align__(16) float sT[NSTATE*NSTATE];
    __shared__ __align__(16) float sT2[NSTATE*NSTATE];

    const int tid = threadIdx.x;

    if (tid < 256) { sM[tid] = M[tid]; sC[tid] = C[tid]; sK[tid] = K[tid]; }
    __syncthreads();

    invert16(sM, sMinv, aug, tid);

    if (tid < 256) sKe[tid] = sM[tid] + 0.5f*DTc*sC[tid] + 0.25f*DTc*DTc*sK[tid];
    __syncthreads();
    invert16(sKe, sAf, aug, tid);

    // A_v = A_f @ C, A_u = A_f @ K
    if (tid < 256) {
        int i = tid >> 4, j = tid & 15;
        float sv = 0.f, su = 0.f;
        #pragma unroll
        for (int k = 0; k < 16; k++) {
            sv = fmaf(sAf[i*16 + k], sC[k*16 + j], sv);
            su = fmaf(sAf[i*16 + k], sK[k*16 + j], su);
        }
        sAv[tid] = sv; sAu[tid] = su;
    }
    __syncthreads();

    if (tid < 256) {
        g_Af[tid] = sAf[tid];
        int i = tid >> 4, j = tid & 15;
        g_Wuv[i*32 + 2*j]     = sAu[tid];
        g_Wuv[i*32 + 2*j + 1] = sAv[tid];
    }

    // Build T (48x48) by pushing state basis vectors through one step (f = 0)
    if (tid < NSTATE) {
        float u[16], v[16], a[16];
        #pragma unroll
        for (int j = 0; j < 16; j++) {
            u[j] = (tid == j)      ? 1.f : 0.f;
            v[j] = (tid == j + 16) ? 1.f : 0.f;
            a[j] = (tid == j + 32) ? 1.f : 0.f;
        }
        float up[16], vp[16], an[16];
        #pragma unroll
        for (int i = 0; i < 16; i++) {
            up[i] = fmaf(CU_, a[i], fmaf(DTc, v[i], u[i]));
            vp[i] = fmaf(CV_, a[i], v[i]);
        }
        #pragma unroll
        for (int i = 0; i < 16; i++) {
            float s = 0.f;
            #pragma unroll
            for (int j = 0; j < 16; j++)
                s = fmaf(sAv[i*16 + j], vp[j], fmaf(sAu[i*16 + j], up[j], s));
            an[i] = -s;
        }
        #pragma unroll
        for (int i = 0; i < 16; i++) {
            sT[(i)     *NSTATE + tid] = fmaf(BU_, an[i], up[i]);
            sT[(16 + i)*NSTATE + tid] = fmaf(BV_, an[i], vp[i]);
            sT[(32 + i)*NSTATE + tid] = an[i];
        }
    }
    __syncthreads();

    // 7 squarings -> T^128 (g_TL)
    float* Asq = sT;
    float* Bsq = sT2;
    for (int it = 0; it < 7; it++) {
        for (int e = tid; e < NSTATE*NSTATE; e += 1024) {
            int r = e / NSTATE, cc = e % NSTATE;
            const float4* rowp = reinterpret_cast<const float4*>(Asq + r*NSTATE);
            float s0 = 0.f, s1 = 0.f, s2 = 0.f, s3 = 0.f;
            #pragma unroll
            for (int q = 0; q < 12; q++) {
                float4 m = rowp[q];
                s0 = fmaf(m.x, Asq[(4*q    )*NSTATE + cc], s0);
                s1 = fmaf(m.y, Asq[(4*q + 1)*NSTATE + cc], s1);
                s2 = fmaf(m.z, Asq[(4*q + 2)*NSTATE + cc], s2);
                s3 = fmaf(m.w, Asq[(4*q + 3)*NSTATE + cc], s3);
            }
            Bsq[e] = (s0 + s1) + (s2 + s3);
        }
        __syncthreads();
        float* t = Asq; Asq = Bsq; Bsq = t;
    }
    for (int e = tid; e < NSTATE*NSTATE; e += 1024) g_TL[e] = Asq[e];

    // a0 = Minv @ F[b,0,:], write init_0 and t=0 output row
    if (tid < BATCH*16) {
        int b = tid >> 4, i = tid & 15;
        const float* f0p = F + (size_t)b * SEQ * N_DOF;
        float s = 0.f;
        #pragma unroll
        for (int j = 0; j < 16; j++) s = fmaf(sMinv[i*16 + j], f0p[j], s);
        float* ip = g_init + (size_t)b * NSTATE;
        ip[i] = 0.f; ip[16 + i] = 0.f; ip[32 + i] = s;
        size_t o = ((size_t)b * SEQ) * N_DOF + i;
        out[o] = 0.f; out[BSD + o] = 0.f; out[2*BSD + o] = s;
    }
}

// ---------------- K_phi: PhiS[b][i][t'] = (Af @ F[b][t'+1])[i], streaming ----------------
__global__ void __launch_bounds__(256) phi_kernel(const float* __restrict__ F)
{
    __shared__ float sAf[256];
    const int tid  = threadIdx.x;
    const int b    = blockIdx.y;
    const int tile = blockIdx.x;           // SEQ/256 tiles
    sAf[tid] = g_Af[tid];
    __syncthreads();

    const int tp = tile * 256 + tid;       // t'
    const int n  = tp + 1;                 // forcing time index

    float ph[16];
    if (n < SEQ) {
        const float4* fp = reinterpret_cast<const float4*>(F + ((size_t)b * SEQ + n) * N_DOF);
        const float4 f0 = fp[0], f1 = fp[1], f2 = fp[2], f3 = fp[3];
        #pragma unroll
        for (int i = 0; i < 16; i++) {
            const float4* ar = reinterpret_cast<const float4*>(sAf + i*16);
            const float4 a0 = ar[0], a1 = ar[1], a2 = ar[2], a3 = ar[3];
            float s0 = 0.f, s1 = 0.f;
            s0 = fmaf(a0.x, f0.x, s0); s1 = fmaf(a0.y, f0.y, s1);
            s0 = fmaf(a0.z, f0.z, s0); s1 = fmaf(a0.w, f0.w, s1);
            s0 = fmaf(a1.x, f1.x, s0); s1 = fmaf(a1.y, f1.y, s1);
            s0 = fmaf(a1.z, f1.z, s0); s1 = fmaf(a1.w, f1.w, s1);
            s0 = fmaf(a2.x, f2.x, s0); s1 = fmaf(a2.y, f2.y, s1);
            s0 = fmaf(a2.z, f2.z, s0); s1 = fmaf(a2.w, f2.w, s1);
            s0 = fmaf(a3.x, f3.x, s0); s1 = fmaf(a3.y, f3.y, s1);
            s0 = fmaf(a3.z, f3.z, s0); s1 = fmaf(a3.w, f3.w, s1);
            ph[i] = s0 + s1;
        }
    } else {
        #pragma unroll
        for (int i = 0; i < 16; i++) ph[i] = 0.f;
    }

    #pragma unroll
    for (int i = 0; i < 16; i++)
        g_PhiS[((size_t)b * N_DOF + i) * SEQ + tp] = ph[i];
}

// ---------------- K1 / K3: chunked scans ----------------
template<bool FINAL>
__global__ void __launch_bounds__(256, 3) scan_kernel(float* __restrict__ out)
{
    const int tid  = threadIdx.x;
    const int lane = tid & 15;
    const int su   = tid >> 4;                 // 0..15
    const int unit = blockIdx.x * 16 + su;
    const int b    = unit & (BATCH - 1);
    const int c    = unit >> 6;

    // exchange weights in registers, packed pairs (Au[j],Av[j])
    const ulonglong2* Wp = reinterpret_cast<const ulonglong2*>(g_Wuv + lane*32);
    const ulonglong2 w0 = Wp[0], w1 = Wp[1], w2 = Wp[2], w3 = Wp[3];
    const ulonglong2 w4 = Wp[4], w5 = Wp[5], w6 = Wp[6], w7 = Wp[7];

    float u, v, a;
    if (FINAL) {
        const float* ip = g_init + ((size_t)c * BATCH + b) * NSTATE;
        u = ip[lane]; v = ip[lane + 16]; a = ip[lane + 32];
    } else {
        u = 0.f; v = 0.f; a = 0.f;
    }

    __shared__ __align__(16) float2 sh[2][16][16];   // double-buffered exchange
    const int t0 = c * CHUNK;

    const float* php = g_PhiS + ((size_t)b * N_DOF + lane) * SEQ + t0;
    float4 ph = *reinterpret_cast<const float4*>(php);   // steps 0..3

    float* outu = out +          ((size_t)b * SEQ + t0 + 1) * N_DOF + lane;
    float* outv = outu + BSD;
    float* outa = outv + BSD;

    #pragma unroll 1
    for (int kg = 0; kg < CHUNK; kg += 4) {
        float4 phn = make_float4(0.f, 0.f, 0.f, 0.f);
        if (kg + 4 < CHUNK) phn = *reinterpret_cast<const float4*>(php + kg + 4);

        #pragma unroll
        for (int s = 0; s < 4; s++) {
            const float phv = (s == 0) ? ph.x : (s == 1) ? ph.y : (s == 2) ? ph.z : ph.w;
            const int buf = s & 1;

            const float up = fmaf(CU_, a, fmaf(DTc, v, u));
            const float vp = fmaf(CV_, a, v);
            sh[buf][su][lane] = make_float2(up, vp);
            __syncwarp();

            const ulonglong2* X2 = reinterpret_cast<const ulonglong2*>(sh[buf][su]);
            u64 accW0 = 0, accW1 = 0;
            {
                ulonglong2 x;
                x = X2[0]; accW0 = ffma2(w0.x, x.x, accW0); accW1 = ffma2(w0.y, x.y, accW1);
                x = X2[1]; accW0 = ffma2(w1.x, x.x, accW0); accW1 = ffma2(w1.y, x.y, accW1);
                x = X2[2]; accW0 = ffma2(w2.x, x.x, accW0); accW1 = ffma2(w2.y, x.y, accW1);
                x = X2[3]; accW0 = ffma2(w3.x, x.x, accW0); accW1 = ffma2(w3.y, x.y, accW1);
                x = X2[4]; accW0 = ffma2(w4.x, x.x, accW0); accW1 = ffma2(w4.y, x.y, accW1);
                x = X2[5]; accW0 = ffma2(w5.x, x.x, accW0); accW1 = ffma2(w5.y, x.y, accW1);
                x = X2[6]; accW0 = ffma2(w6.x, x.x, accW0); accW1 = ffma2(w6.y, x.y, accW1);
                x = X2[7]; accW0 = ffma2(w7.x, x.x, accW0); accW1 = ffma2(w7.y, x.y, accW1);
            }
            const float2 wS = unpack2(fadd2(accW0, accW1));
            const float an = phv - wS.x - wS.y;
            const float un = fmaf(BU_, an, up);
            const float vn = fmaf(BV_, an, vp);

            if (FINAL) {
                const int t = t0 + kg + s + 1;
                if (t < SEQ) {
                    const size_t off = (size_t)(kg + s) * N_DOF;
                    __stcs(outu + off, un);
                    __stcs(outv + off, vn);
                    __stcs(outa + off, an);
                }
            }
            u = un; v = vn; a = an;
        }
        ph = phn;
    }

    if (!FINAL) {
        float* ep = g_e + ((size_t)c * BATCH + b) * NSTATE;
        ep[lane] = u; ep[lane + 16] = v; ep[lane + 32] = a;
    }
}

// ---------------- K2: sequential chunk chain (per batch, SMEM-staged) ----------------
__global__ void __launch_bounds__(128) chain_kernel()
{
    const int b = blockIdx.x;
    const int tid = threadIdx.x;      // 0..127
    const int i = tid;                // compute lane (only < NSTATE active)

    __shared__ __align__(16) float se[(NCHUNK-1)*NSTATE];   // 63*48*4 = 12096 B
    __shared__ __align__(16) float cur[2][NSTATE];

    // bulk stage: g_e[c][b][:] for all c -> SMEM (high MLP, coalesced 192B rows)
    for (int idx = tid; idx < (NCHUNK-1)*NSTATE; idx += 128) {
        const int c = idx / NSTATE;
        const int j = idx - c * NSTATE;
        se[idx] = g_e[((size_t)c * BATCH + b) * NSTATE + j];
    }

    // T row as 24 packed pairs (threads < NSTATE)
    ulonglong2 tl[12];
    if (i < NSTATE) {
        const ulonglong2* tp = reinterpret_cast<const ulonglong2*>(g_TL + i*NSTATE);
        #pragma unroll
        for (int q = 0; q < 12; q++) tl[q] = tp[q];
        cur[0][i] = g_init[(size_t)b * NSTATE + i];
    }
    __syncthreads();

    int p = 0;
    for (int c = 1; c < NCHUNK; c++) {
        if (i < NSTATE) {
            const float ev = se[(c - 1) * NSTATE + i];
            const ulonglong2* c2 = reinterpret_cast<const ulonglong2*>(cur[p]);
            u64 a0 = 0, a1 = 0, a2 = 0, a3 = 0;
            #pragma unroll
            for (int q = 0; q < 12; q += 4) {
                ulonglong2 x;
                x = c2[q];     a0 = ffma2(tl[q].x,     x.x, a0); a1 = ffma2(tl[q].y,     x.y, a1);
                x = c2[q + 1]; a2 = ffma2(tl[q + 1].x, x.x, a2); a3 = ffma2(tl[q + 1].y, x.y, a3);
                x = c2[q + 2]; a0 = ffma2(tl[q + 2].x, x.x, a0); a1 = ffma2(tl[q + 2].y, x.y, a1);
                x = c2[q + 3]; a2 = ffma2(tl[q + 3].x, x.x, a2); a3 = ffma2(tl[q + 3].y, x.y, a3);
            }
            const float2 s01 = unpack2(fadd2(a0, a1));
            const float2 s23 = unpack2(fadd2(a2, a3));
            const float r = ((s01.x + s01.y) + (s23.x + s23.y)) + ev;
            g_init[((size_t)c * BATCH + b) * NSTATE + i] = r;
            cur[1 - p][i] = r;
        }
        __syncthreads();
        p ^= 1;
    }
}

// ---------------- launch ----------------
extern "C" void kernel_launch(void* const* d_in, const int* in_sizes, int n_in,
                              void* d_out, int out_size)
{
    const float* F = (const float*)d_in[0];
    const float* M = (const float*)d_in[1];
    const float* C = (const float*)d_in[2];
    const float* K = (const float*)d_in[3];
    float* out = (float*)d_out;

    setup_kernel<<<1, 1024>>>(F, M, C, K, out);

    // forcing precompute: PhiS = Af @ F rows, transposed + shifted
    phi_kernel<<<dim3(SEQ/256, BATCH), 256>>>(F);

    // K1: zero-init local scans for chunks 0..NCHUNK-2
    scan_kernel<false><<<(NCHUNK - 1) * BATCH / 16, 256>>>(nullptr);

    // K2: sequential combine across chunks, independent per batch
    chain_kernel<<<BATCH, 128>>>();

    // K3: final scans from correct initial states, all chunks
    scan_kernel<true><<<NCHUNK * BATCH / 16, 256>>>(out);
}

// round 11
// speedup vs baseline: 1.0875x; 1.0007x over previous
#include <cuda_runtime.h>

#define N_DOF 16
#define BATCH 64
#define SEQ 8192
#define CHUNK 128
#define NCHUNK (SEQ/CHUNK)          // 64
#define NSTATE 48
#define BSD ((size_t)BATCH*(size_t)SEQ*(size_t)N_DOF)

#define DTc 0.01f
#define CU_ 2.5e-5f   // (0.5-beta)*dt*dt
#define CV_ 0.005f    // (1-gamma)*dt
#define BU_ 2.5e-5f   // beta*dt*dt
#define BV_ 0.005f    // gamma*dt

// ---------------- packed f32x2 helpers (Blackwell FFMA2) ----------------
typedef unsigned long long u64;

__device__ __forceinline__ u64 ffma2(u64 a, u64 b, u64 c) {
    u64 d;
    asm("fma.rn.f32x2 %0, %1, %2, %3;" : "=l"(d) : "l"(a), "l"(b), "l"(c));
    return d;
}
__device__ __forceinline__ u64 fadd2(u64 a, u64 b) {
    u64 d;
    asm("add.rn.f32x2 %0, %1, %2;" : "=l"(d) : "l"(a), "l"(b));
    return d;
}
__device__ __forceinline__ float2 unpack2(u64 d) {
    float2 f;
    asm("mov.b64 {%0, %1}, %2;" : "=f"(f.x), "=f"(f.y) : "l"(d));
    return f;
}

// ---------------- scratch (device globals; no runtime allocation) ----------------
__device__ __align__(16) float g_Af[256];      // K_eff^{-1}
__device__ __align__(16) float g_Wuv[16*32];   // interleaved pairs: (Au[i][j], Av[i][j])
__device__ __align__(16) float g_TL[NSTATE*NSTATE];    // T^CHUNK
__device__ __align__(16) float g_e[(NCHUNK-1)*BATCH*NSTATE];
__device__ __align__(16) float g_init[NCHUNK*BATCH*NSTATE];
// PhiS[b][i][t'] = (A_f @ F[b, t'+1, :])[i]  for t' in [0, SEQ-1); PhiS[..][SEQ-1] = 0
__device__ __align__(16) float g_PhiS[(size_t)BATCH*N_DOF*SEQ];

// ---------------- K0: setup ----------------
__device__ void invert16(const float* A, float* Ainv, double (*aug)[34], int tid)
{
    if (tid < 16) {
        #pragma unroll
        for (int j = 0; j < 16; j++) {
            aug[tid][j]      = (double)A[tid*16 + j];
            aug[tid][16 + j] = (tid == j) ? 1.0 : 0.0;
        }
    }
    __syncthreads();
    for (int k = 0; k < 16; k++) {
        if (tid == k) {
            double p = 1.0 / aug[k][k];
            #pragma unroll
            for (int j = 0; j < 32; j++) aug[k][j] *= p;
        }
        __syncthreads();
        if (tid < 16 && tid != k) {
            double f = aug[tid][k];
            #pragma unroll
            for (int j = 0; j < 32; j++) aug[tid][j] -= f * aug[k][j];
        }
        __syncthreads();
    }
    if (tid < 16) {
        #pragma unroll
        for (int j = 0; j < 16; j++) Ainv[tid*16 + j] = (float)aug[tid][16 + j];
    }
    __syncthreads();
}

__global__ void __launch_bounds__(1024) setup_kernel(const float* __restrict__ F,
                             const float* __restrict__ M,
                             const float* __restrict__ C,
                             const float* __restrict__ K,
                             float* __restrict__ out)
{
    __shared__ double aug[16][34];
    __shared__ float sM[256], sC[256], sK[256], sKe[256];
    __shared__ float sMinv[256], sAf[256], sAv[256], sAu[256];
    __shared__ __align__(16) float sT[NSTATE*NSTATE];
    __shared__ __align__(16) float sT2[NSTATE*NSTATE];

    const int tid = threadIdx.x;

    if (tid < 256) { sM[tid] = M[tid]; sC[tid] = C[tid]; sK[tid] = K[tid]; }
    __syncthreads();

    invert16(sM, sMinv, aug, tid);

    if (tid < 256) sKe[tid] = sM[tid] + 0.5f*DTc*sC[tid] + 0.25f*DTc*DTc*sK[tid];
    __syncthreads();
    invert16(sKe, sAf, aug, tid);

    // A_v = A_f @ C, A_u = A_f @ K
    if (tid < 256) {
        int i = tid >> 4, j = tid & 15;
        float sv = 0.f, su = 0.f;
        #pragma unroll
        for (int k = 0; k < 16; k++) {
            sv = fmaf(sAf[i*16 + k], sC[k*16 + j], sv);
            su = fmaf(sAf[i*16 + k], sK[k*16 + j], su);
        }
        sAv[tid] = sv; sAu[tid] = su;
    }
    __syncthreads();

    if (tid < 256) {
        g_Af[tid] = sAf[tid];
        int i = tid >> 4, j = tid & 15;
        g_Wuv[i*32 + 2*j]     = sAu[tid];
        g_Wuv[i*32 + 2*j + 1] = sAv[tid];
    }

    // Build T (48x48) by pushing state basis vectors through one step (f = 0)
    if (tid < NSTATE) {
        float u[16], v[16], a[16];
        #pragma unroll
        for (int j = 0; j < 16; j++) {
            u[j] = (tid == j)      ? 1.f : 0.f;
            v[j] = (tid == j + 16) ? 1.f : 0.f;
            a[j] = (tid == j + 32) ? 1.f : 0.f;
        }
        float up[16], vp[16], an[16];
        #pragma unroll
        for (int i = 0; i < 16; i++) {
            up[i] = fmaf(CU_, a[i], fmaf(DTc, v[i], u[i]));
            vp[i] = fmaf(CV_, a[i], v[i]);
        }
        #pragma unroll
        for (int i = 0; i < 16; i++) {
            float s = 0.f;
            #pragma unroll
            for (int j = 0; j < 16; j++)
                s = fmaf(sAv[i*16 + j], vp[j], fmaf(sAu[i*16 + j], up[j], s));
            an[i] = -s;
        }
        #pragma unroll
        for (int i = 0; i < 16; i++) {
            sT[(i)     *NSTATE + tid] = fmaf(BU_, an[i], up[i]);
            sT[(16 + i)*NSTATE + tid] = fmaf(BV_, an[i], vp[i]);
            sT[(32 + i)*NSTATE + tid] = an[i];
        }
    }
    __syncthreads();

    // 7 squarings -> T^128 (g_TL)
    float* Asq = sT;
    float* Bsq = sT2;
    for (int it = 0; it < 7; it++) {
        for (int e = tid; e < NSTATE*NSTATE; e += 1024) {
            int r = e / NSTATE, cc = e % NSTATE;
            const float4* rowp = reinterpret_cast<const float4*>(Asq + r*NSTATE);
            float s0 = 0.f, s1 = 0.f, s2 = 0.f, s3 = 0.f;
            #pragma unroll
            for (int q = 0; q < 12; q++) {
                float4 m = rowp[q];
                s0 = fmaf(m.x, Asq[(4*q    )*NSTATE + cc], s0);
                s1 = fmaf(m.y, Asq[(4*q + 1)*NSTATE + cc], s1);
                s2 = fmaf(m.z, Asq[(4*q + 2)*NSTATE + cc], s2);
                s3 = fmaf(m.w, Asq[(4*q + 3)*NSTATE + cc], s3);
            }
            Bsq[e] = (s0 + s1) + (s2 + s3);
        }
        __syncthreads();
        float* t = Asq; Asq = Bsq; Bsq = t;
    }
    for (int e = tid; e < NSTATE*NSTATE; e += 1024) g_TL[e] = Asq[e];

    // a0 = Minv @ F[b,0,:], write init_0 and t=0 output row
    if (tid < BATCH*16) {
        int b = tid >> 4, i = tid & 15;
        const float* f0p = F + (size_t)b * SEQ * N_DOF;
        float s = 0.f;
        #pragma unroll
        for (int j = 0; j < 16; j++) s = fmaf(sMinv[i*16 + j], f0p[j], s);
        float* ip = g_init + (size_t)b * NSTATE;
        ip[i] = 0.f; ip[16 + i] = 0.f; ip[32 + i] = s;
        size_t o = ((size_t)b * SEQ) * N_DOF + i;
        out[o] = 0.f; out[BSD + o] = 0.f; out[2*BSD + o] = s;
    }
}

// ---------------- K_phi: PhiS[b][i][t'] = (Af @ F[b][t'+1])[i], streaming ----------------
__global__ void __launch_bounds__(256) phi_kernel(const float* __restrict__ F)
{
    __shared__ float sAf[256];
    const int tid  = threadIdx.x;
    const int b    = blockIdx.y;
    const int tile = blockIdx.x;           // SEQ/256 tiles
    sAf[tid] = g_Af[tid];
    __syncthreads();

    const int tp = tile * 256 + tid;       // t'
    const int n  = tp + 1;                 // forcing time index

    float ph[16];
    if (n < SEQ) {
        const float4* fp = reinterpret_cast<const float4*>(F + ((size_t)b * SEQ + n) * N_DOF);
        const float4 f0 = fp[0], f1 = fp[1], f2 = fp[2], f3 = fp[3];
        #pragma unroll
        for (int i = 0; i < 16; i++) {
            const float4* ar = reinterpret_cast<const float4*>(sAf + i*16);
            const float4 a0 = ar[0], a1 = ar[1], a2 = ar[2], a3 = ar[3];
            float s0 = 0.f, s1 = 0.f;
            s0 = fmaf(a0.x, f0.x, s0); s1 = fmaf(a0.y, f0.y, s1);
            s0 = fmaf(a0.z, f0.z, s0); s1 = fmaf(a0.w, f0.w, s1);
            s0 = fmaf(a1.x, f1.x, s0); s1 = fmaf(a1.y, f1.y, s1);
            s0 = fmaf(a1.z, f1.z, s0); s1 = fmaf(a1.w, f1.w, s1);
            s0 = fmaf(a2.x, f2.x, s0); s1 = fmaf(a2.y, f2.y, s1);
            s0 = fmaf(a2.z, f2.z, s0); s1 = fmaf(a2.w, f2.w, s1);
            s0 = fmaf(a3.x, f3.x, s0); s1 = fmaf(a3.y, f3.y, s1);
            s0 = fmaf(a3.z, f3.z, s0); s1 = fmaf(a3.w, f3.w, s1);
            ph[i] = s0 + s1;
        }
    } else {
        #pragma unroll
        for (int i = 0; i < 16; i++) ph[i] = 0.f;
    }

    #pragma unroll
    for (int i = 0; i < 16; i++)
        g_PhiS[((size_t)b * N_DOF + i) * SEQ + tp] = ph[i];
}

// ---------------- K1 / K3: chunked scans, 2 independent units per thread ----------------
template<bool FINAL>
__global__ void __launch_bounds__(128, 4) scan_kernel(float* __restrict__ out)
{
    const int tid  = threadIdx.x;
    const int lane = tid & 15;
    const int grp  = tid >> 4;                 // 0..7
    const int unitA = blockIdx.x * 16 + grp;
    const int unitB = unitA + 8;
    const int bA = unitA & (BATCH - 1), cA = unitA >> 6;
    const int bB = unitB & (BATCH - 1), cB = unitB >> 6;

    // exchange weights in registers, packed pairs (Au[j],Av[j]) — shared by A and B
    const ulonglong2* Wp = reinterpret_cast<const ulonglong2*>(g_Wuv + lane*32);
    const ulonglong2 w0 = Wp[0], w1 = Wp[1], w2 = Wp[2], w3 = Wp[3];
    const ulonglong2 w4 = Wp[4], w5 = Wp[5], w6 = Wp[6], w7 = Wp[7];

    float uA, vA, aA, uB, vB, aB;
    if (FINAL) {
        const float* ipA = g_init + ((size_t)cA * BATCH + bA) * NSTATE;
        uA = ipA[lane]; vA = ipA[lane + 16]; aA = ipA[lane + 32];
        const float* ipB = g_init + ((size_t)cB * BATCH + bB) * NSTATE;
        uB = ipB[lane]; vB = ipB[lane + 16]; aB = ipB[lane + 32];
    } else {
        uA = vA = aA = 0.f;
        uB = vB = aB = 0.f;
    }

    __shared__ __align__(16) float2 sh[2][16][16];   // [buf][slot][lane]; slotA=grp, slotB=grp+8
    const int tA0 = cA * CHUNK;
    const int tB0 = cB * CHUNK;

    const float* phpA = g_PhiS + ((size_t)bA * N_DOF + lane) * SEQ + tA0;
    const float* phpB = g_PhiS + ((size_t)bB * N_DOF + lane) * SEQ + tB0;
    float4 phA = *reinterpret_cast<const float4*>(phpA);
    float4 phB = *reinterpret_cast<const float4*>(phpB);

    float* outuA = out +          ((size_t)bA * SEQ + tA0 + 1) * N_DOF + lane;
    float* outuB = out +          ((size_t)bB * SEQ + tB0 + 1) * N_DOF + lane;

    #pragma unroll 1
    for (int kg = 0; kg < CHUNK; kg += 4) {
        float4 phnA = make_float4(0.f, 0.f, 0.f, 0.f);
        float4 phnB = make_float4(0.f, 0.f, 0.f, 0.f);
        if (kg + 4 < CHUNK) {
            phnA = *reinterpret_cast<const float4*>(phpA + kg + 4);
            phnB = *reinterpret_cast<const float4*>(phpB + kg + 4);
        }

        #pragma unroll
        for (int s = 0; s < 4; s++) {
            const float phvA = (s == 0) ? phA.x : (s == 1) ? phA.y : (s == 2) ? phA.z : phA.w;
            const float phvB = (s == 0) ? phB.x : (s == 1) ? phB.y : (s == 2) ? phB.z : phB.w;
            const int buf = s & 1;

            const float upA = fmaf(CU_, aA, fmaf(DTc, vA, uA));
            const float vpA = fmaf(CV_, aA, vA);
            const float upB = fmaf(CU_, aB, fmaf(DTc, vB, uB));
            const float vpB = fmaf(CV_, aB, vB);
            sh[buf][grp][lane]     = make_float2(upA, vpA);
            sh[buf][grp + 8][lane] = make_float2(upB, vpB);
            __syncwarp();

            const ulonglong2* XA = reinterpret_cast<const ulonglong2*>(sh[buf][grp]);
            const ulonglong2* XB = reinterpret_cast<const ulonglong2*>(sh[buf][grp + 8]);
            u64 aW0 = 0, aW1 = 0, bW0 = 0, bW1 = 0;
            {
                ulonglong2 x, y;
                x = XA[0]; y = XB[0];
                aW0 = ffma2(w0.x, x.x, aW0); aW1 = ffma2(w0.y, x.y, aW1);
                bW0 = ffma2(w0.x, y.x, bW0); bW1 = ffma2(w0.y, y.y, bW1);
                x = XA[1]; y = XB[1];
                aW0 = ffma2(w1.x, x.x, aW0); aW1 = ffma2(w1.y, x.y, aW1);
                bW0 = ffma2(w1.x, y.x, bW0); bW1 = ffma2(w1.y, y.y, bW1);
                x = XA[2]; y = XB[2];
                aW0 = ffma2(w2.x, x.x, aW0); aW1 = ffma2(w2.y, x.y, aW1);
                bW0 = ffma2(w2.x, y.x, bW0); bW1 = ffma2(w2.y, y.y, bW1);
                x = XA[3]; y = XB[3];
                aW0 = ffma2(w3.x, x.x, aW0); aW1 = ffma2(w3.y, x.y, aW1);
                bW0 = ffma2(w3.x, y.x, bW0); bW1 = ffma2(w3.y, y.y, bW1);
                x = XA[4]; y = XB[4];
                aW0 = ffma2(w4.x, x.x, aW0); aW1 = ffma2(w4.y, x.y, aW1);
                bW0 = ffma2(w4.x, y.x, bW0); bW1 = ffma2(w4.y, y.y, bW1);
                x = XA[5]; y = XB[5];
                aW0 = ffma2(w5.x, x.x, aW0); aW1 = ffma2(w5.y, x.y, aW1);
                bW0 = ffma2(w5.x, y.x, bW0); bW1 = ffma2(w5.y, y.y, bW1);
                x = XA[6]; y = XB[6];
                aW0 = ffma2(w6.x, x.x, aW0); aW1 = ffma2(w6.y, x.y, aW1);
                bW0 = ffma2(w6.x, y.x, bW0); bW1 = ffma2(w6.y, y.y, bW1);
                x = XA[7]; y = XB[7];
                aW0 = ffma2(w7.x, x.x, aW0); aW1 = ffma2(w7.y, x.y, aW1);
                bW0 = ffma2(w7.x, y.x, bW0); bW1 = ffma2(w7.y, y.y, bW1);
            }
            const float2 wSA = unpack2(fadd2(aW0, aW1));
            const float2 wSB = unpack2(fadd2(bW0, bW1));
            const float anA = phvA - wSA.x - wSA.y;
            const float anB = phvB - wSB.x - wSB.y;
            const float unA = fmaf(BU_, anA, upA);
            const float vnA = fmaf(BV_, anA, vpA);
            const float unB = fmaf(BU_, anB, upB);
            const float vnB = fmaf(BV_, anB, vpB);

            if (FINAL) {
                const size_t off = (size_t)(kg + s) * N_DOF;
                if (tA0 + kg + s + 1 < SEQ) {
                    __stcs(outuA + off, unA);
                    __stcs(outuA + BSD + off, vnA);
                    __stcs(outuA + 2*BSD + off, anA);
                }
                if (tB0 + kg + s + 1 < SEQ) {
                    __stcs(outuB + off, unB);
                    __stcs(outuB + BSD + off, vnB);
                    __stcs(outuB + 2*BSD + off, anB);
                }
            }
            uA = unA; vA = vnA; aA = anA;
            uB = unB; vB = vnB; aB = anB;
        }
        phA = phnA;
        phB = phnB;
    }

    if (!FINAL) {
        float* epA = g_e + ((size_t)cA * BATCH + bA) * NSTATE;
        epA[lane] = uA; epA[lane + 16] = vA; epA[lane + 32] = aA;
        float* epB = g_e + ((size_t)cB * BATCH + bB) * NSTATE;
        epB[lane] = uB; epB[lane + 16] = vB; epB[lane + 32] = aB;
    }
}

// ---------------- K2: sequential chunk chain (per batch, SMEM-staged) ----------------
__global__ void __launch_bounds__(128) chain_kernel()
{
    const int b = blockIdx.x;
    const int tid = threadIdx.x;      // 0..127
    const int i = tid;                // compute lane (only < NSTATE active)

    __shared__ __align__(16) float se[(NCHUNK-1)*NSTATE];   // 63*48*4 = 12096 B
    __shared__ __align__(16) float cur[2][NSTATE];

    // bulk stage: g_e[c][b][:] for all c -> SMEM (high MLP, coalesced 192B rows)
    for (int idx = tid; idx < (NCHUNK-1)*NSTATE; idx += 128) {
        const int c = idx / NSTATE;
        const int j = idx - c * NSTATE;
        se[idx] = g_e[((size_t)c * BATCH + b) * NSTATE + j];
    }

    // T row as 24 packed pairs (threads < NSTATE)
    ulonglong2 tl[12];
    if (i < NSTATE) {
        const ulonglong2* tp = reinterpret_cast<const ulonglong2*>(g_TL + i*NSTATE);
        #pragma unroll
        for (int q = 0; q < 12; q++) tl[q] = tp[q];
        cur[0][i] = g_init[(size_t)b * NSTATE + i];
    }
    __syncthreads();

    int p = 0;
    for (int c = 1; c < NCHUNK; c++) {
        if (i < NSTATE) {
            const float ev = se[(c - 1) * NSTATE + i];
            const ulonglong2* c2 = reinterpret_cast<const ulonglong2*>(cur[p]);
            u64 a0 = 0, a1 = 0, a2 = 0, a3 = 0;
            #pragma unroll
            for (int q = 0; q < 12; q += 4) {
                ulonglong2 x;
                x = c2[q];     a0 = ffma2(tl[q].x,     x.x, a0); a1 = ffma2(tl[q].y,     x.y, a1);
                x = c2[q + 1]; a2 = ffma2(tl[q + 1].x, x.x, a2); a3 = ffma2(tl[q + 1].y, x.y, a3);
                x = c2[q + 2]; a0 = ffma2(tl[q + 2].x, x.x, a0); a1 = ffma2(tl[q + 2].y, x.y, a1);
                x = c2[q + 3]; a2 = ffma2(tl[q + 3].x, x.x, a2); a3 = ffma2(tl[q + 3].y, x.y, a3);
            }
            const float2 s01 = unpack2(fadd2(a0, a1));
            const float2 s23 = unpack2(fadd2(a2, a3));
            const float r = ((s01.x + s01.y) + (s23.x + s23.y)) + ev;
            g_init[((size_t)c * BATCH + b) * NSTATE + i] = r;
            cur[1 - p][i] = r;
        }
        __syncthreads();
        p ^= 1;
    }
}

// ---------------- launch ----------------
extern "C" void kernel_launch(void* const* d_in, const int* in_sizes, int n_in,
                              void* d_out, int out_size)
{
    const float* F = (const float*)d_in[0];
    const float* M = (const float*)d_in[1];
    const float* C = (const float*)d_in[2];
    const float* K = (const float*)d_in[3];
    float* out = (float*)d_out;

    setup_kernel<<<1, 1024>>>(F, M, C, K, out);

    // forcing precompute: PhiS = Af @ F rows, transposed + shifted
    phi_kernel<<<dim3(SEQ/256, BATCH), 256>>>(F);

    // K1: zero-init local scans for chunks 0..NCHUNK-2 (4032 units, 16/block)
    scan_kernel<false><<<(NCHUNK - 1) * BATCH / 16, 128>>>(nullptr);

    // K2: sequential combine across chunks, independent per batch
    chain_kernel<<<BATCH, 128>>>();

    // K3: final scans from correct initial states (4096 units, 16/block)
    scan_kernel<true><<<NCHUNK * BATCH / 16, 128>>>(out);
}